// round 1
// baseline (speedup 1.0000x reference)
#include <cuda_runtime.h>
#include <math.h>

// Problem constants (fixed shape for this problem)
#define NROWS   262144
#define DIMK    128
#define MFEAT   256

// ---------------- scratch (no allocations allowed -> device globals) -------
__device__ float    g_UK[(size_t)NROWS * MFEAT];   // U_K, overwritten with Kp
__device__ float    g_UQ[(size_t)NROWS * MFEAT];   // U_Q
__device__ float    g_hK[NROWS];
__device__ float    g_hQ[NROWS];
__device__ float    g_Ksum[MFEAT];
__device__ unsigned g_maxbits;

// monotonic float<->uint mapping for atomicMax on floats (handles negatives)
__device__ __forceinline__ unsigned fkey(float f) {
    unsigned b = __float_as_uint(f);
    return (b & 0x80000000u) ? ~b : (b | 0x80000000u);
}
__device__ __forceinline__ float fdecode(unsigned u) {
    return (u & 0x80000000u) ? __uint_as_float(u & 0x7FFFFFFFu)
                             : __uint_as_float(~u);
}

// ---------------- kernel 0: reset accumulators ------------------------------
__global__ void init_kernel() {
    int t = threadIdx.x;
    if (t < MFEAT) g_Ksum[t] = 0.0f;
    if (t == 0)    g_maxbits = 0u;   // decodes below any real float key
}

// ---------------- kernel 1/3: U = (X * d^-1/4) @ omega, h = sum(x^2)/(2 sqrt d)
// one thread per row; omega staged in dynamic SMEM (128*256*4 = 128 KB)
__global__ __launch_bounds__(256, 1)
void gemm_phi_pre(const float* __restrict__ X,
                  float* __restrict__ U,
                  float* __restrict__ hout,
                  const float* __restrict__ omega,
                  int trackMax) {
    extern __shared__ float s_w[];   // [DIMK][MFEAT]
    // cooperative omega load (float4)
    for (int i = threadIdx.x; i < DIMK * MFEAT / 4; i += blockDim.x)
        ((float4*)s_w)[i] = ((const float4*)omega)[i];
    __syncthreads();

    const int row = blockIdx.x * blockDim.x + threadIdx.x;
    const float invD4 = 0.2973017787506803f;     // 128^-0.25

    float x[DIMK];
    float h = 0.0f;
    {
        const float4* xr = (const float4*)(X + (size_t)row * DIMK);
        #pragma unroll
        for (int i = 0; i < DIMK / 4; ++i) {
            float4 v = xr[i];
            v.x *= invD4; v.y *= invD4; v.z *= invD4; v.w *= invD4;
            x[4*i+0] = v.x; x[4*i+1] = v.y; x[4*i+2] = v.z; x[4*i+3] = v.w;
            h += v.x*v.x + v.y*v.y + v.z*v.z + v.w*v.w;
        }
    }
    // sum((x/d^.25)^2) = sum(x^2)/sqrt(d)  ->  h = sum(x^2)/(2 sqrt d) = 0.5*that
    h *= 0.5f;
    hout[row] = h;

    float rowmax = -INFINITY;
    float* urow = U + (size_t)row * MFEAT;

    for (int f0 = 0; f0 < MFEAT; f0 += 8) {
        float a0=0.f,a1=0.f,a2=0.f,a3=0.f,a4=0.f,a5=0.f,a6=0.f,a7=0.f;
        #pragma unroll
        for (int k = 0; k < DIMK; ++k) {
            const float4 w0 = *(const float4*)&s_w[k * MFEAT + f0];
            const float4 w1 = *(const float4*)&s_w[k * MFEAT + f0 + 4];
            const float xv = x[k];
            a0 += xv * w0.x; a1 += xv * w0.y; a2 += xv * w0.z; a3 += xv * w0.w;
            a4 += xv * w1.x; a5 += xv * w1.y; a6 += xv * w1.z; a7 += xv * w1.w;
        }
        float4 o0 = make_float4(a0, a1, a2, a3);
        float4 o1 = make_float4(a4, a5, a6, a7);
        *(float4*)&urow[f0]     = o0;
        *(float4*)&urow[f0 + 4] = o1;
        if (trackMax) {
            rowmax = fmaxf(rowmax, fmaxf(fmaxf(a0,a1), fmaxf(a2,a3)));
            rowmax = fmaxf(rowmax, fmaxf(fmaxf(a4,a5), fmaxf(a6,a7)));
        }
    }

    if (trackMax) {
        // warp reduce, then block reduce via static shared, one atomic/block
        __shared__ float s_red[8];
        #pragma unroll
        for (int o = 16; o > 0; o >>= 1)
            rowmax = fmaxf(rowmax, __shfl_xor_sync(0xFFFFFFFFu, rowmax, o));
        const int wid = threadIdx.x >> 5;
        if ((threadIdx.x & 31) == 0) s_red[wid] = rowmax;
        __syncthreads();
        if (threadIdx.x == 0) {
            float bm = s_red[0];
            #pragma unroll
            for (int i = 1; i < 8; ++i) bm = fmaxf(bm, s_red[i]);
            atomicMax(&g_maxbits, fkey(bm));
        }
    }
}

// ---------------- kernel 2: Kp = (exp(U - h - M) + 1e-4)/16 (in place) + Ksum
#define KP_ROWS 256
__global__ void kp_kernel() {
    const int f  = threadIdx.x;                 // 256 threads = 256 features
    const int r0 = blockIdx.x * KP_ROWS;
    const float M = fdecode(g_maxbits);
    float sum = 0.0f;
    for (int i = 0; i < KP_ROWS; ++i) {
        const int r = r0 + i;
        const size_t idx = (size_t)r * MFEAT + f;
        const float u  = g_UK[idx];
        const float kp = (__expf(u - g_hK[r] - M) * 0.0f + expf(u - g_hK[r] - M) + 1e-4f) * 0.0625f;
        g_UK[idx] = kp;
        sum += kp;
    }
    atomicAdd(&g_Ksum[f], sum);
}

// ---------------- kernel 4: fused epilogue, one warp per row ---------------
__global__ void final_kernel(const float* __restrict__ V,
                             float* __restrict__ out) {
    const int gwarp = (blockIdx.x * blockDim.x + threadIdx.x) >> 5;  // row
    const int lane  = threadIdx.x & 31;
    const size_t base = (size_t)gwarp * MFEAT;

    float u[8];
    float mx = -INFINITY;
    #pragma unroll
    for (int j = 0; j < 8; ++j) {
        u[j] = g_UQ[base + lane + 32 * j];
        mx = fmaxf(mx, u[j]);
    }
    #pragma unroll
    for (int o = 16; o > 0; o >>= 1)
        mx = fmaxf(mx, __shfl_xor_sync(0xFFFFFFFFu, mx, o));

    const float h = g_hQ[gwarp];
    float w = 0.0f, nrm = 0.0f;
    #pragma unroll
    for (int j = 0; j < 8; ++j) {
        const float qp = (expf(u[j] - h - mx) + 1e-4f) * 0.0625f;
        w   += qp * g_UK[base + lane + 32 * j];   // g_UK now holds Kp
        nrm += qp * g_Ksum[lane + 32 * j];
    }
    #pragma unroll
    for (int o = 16; o > 0; o >>= 1) {
        w   += __shfl_xor_sync(0xFFFFFFFFu, w,   o);
        nrm += __shfl_xor_sync(0xFFFFFFFFu, nrm, o);
    }
    nrm += 1e-8f;
    const float scale = w / nrm;

    // 128 floats / row = 32 float4 -> exactly one per lane
    const float4 v4 = ((const float4*)(V + (size_t)gwarp * DIMK))[lane];
    float4 o4;
    o4.x = v4.x * scale; o4.y = v4.y * scale;
    o4.z = v4.z * scale; o4.w = v4.w * scale;
    ((float4*)(out + (size_t)gwarp * DIMK))[lane] = o4;
}

// ---------------- launch ----------------------------------------------------
extern "C" void kernel_launch(void* const* d_in, const int* in_sizes, int n_in,
                              void* d_out, int out_size) {
    const float* Q     = (const float*)d_in[0];
    const float* K     = (const float*)d_in[1];
    const float* V     = (const float*)d_in[2];
    const float* omega = (const float*)d_in[3];
    float* out = (float*)d_out;

    const int smem = DIMK * MFEAT * (int)sizeof(float);   // 128 KB
    cudaFuncSetAttribute(gemm_phi_pre,
                         cudaFuncAttributeMaxDynamicSharedMemorySize, smem);

    float* UK = nullptr; float* UQ = nullptr;
    float* hK = nullptr; float* hQ = nullptr;
    cudaGetSymbolAddress((void**)&UK, g_UK);
    cudaGetSymbolAddress((void**)&UQ, g_UQ);
    cudaGetSymbolAddress((void**)&hK, g_hK);
    cudaGetSymbolAddress((void**)&hQ, g_hQ);

    init_kernel<<<1, 256>>>();
    gemm_phi_pre<<<NROWS / 256, 256, smem>>>(K, UK, hK, omega, 1);
    kp_kernel<<<NROWS / KP_ROWS, 256>>>();
    gemm_phi_pre<<<NROWS / 256, 256, smem>>>(Q, UQ, hQ, omega, 0);
    final_kernel<<<NROWS / 8, 256>>>(V, out);
}

// round 4
// speedup vs baseline: 3.0096x; 3.0096x over previous
#include <cuda_runtime.h>
#include <cuda_bf16.h>
#include <math.h>

// Problem constants
#define NROWS   262144
#define DIMK    128
#define MFEAT   256

#define SX_STRIDE 136   // bf16 elements per X row in smem (padded: conflict-free frags)
#define SO_STRIDE 136   // bf16 elements per omegaT row in smem

// ---------------- scratch (device globals; no allocations allowed) ----------
__device__ float         g_UK[(size_t)NROWS * MFEAT];   // U_K, later Kp in-place
__device__ float         g_UQ[(size_t)NROWS * MFEAT];
__device__ float         g_hK[NROWS];
__device__ float         g_hQ[NROWS];
__device__ float         g_Ksum[MFEAT];
__device__ unsigned      g_maxbits;
__device__ __nv_bfloat16 g_omTh[MFEAT * DIMK];          // omega^T hi  [feat][k]
__device__ __nv_bfloat16 g_omTl[MFEAT * DIMK];          // omega^T lo  [feat][k]

// monotonic float<->uint mapping for atomicMax on floats
__device__ __forceinline__ unsigned fkey(float f) {
    unsigned b = __float_as_uint(f);
    return (b & 0x80000000u) ? ~b : (b | 0x80000000u);
}
__device__ __forceinline__ float fdecode(unsigned u) {
    return (u & 0x80000000u) ? __uint_as_float(u & 0x7FFFFFFFu)
                             : __uint_as_float(~u);
}

// ---------------- kernel 0: build omega^T bf16 splits + reset accumulators --
__global__ void init_kernel(const float* __restrict__ omega) {
    const int idx = blockIdx.x * 256 + threadIdx.x;   // 0..32767
    const int k = idx >> 8;        // omega is [DIMK][MFEAT] row-major
    const int m = idx & 255;
    const float w = omega[idx];
    const __nv_bfloat16 hi = __float2bfloat16(w);
    const float lo = w - __bfloat162float(hi);
    g_omTh[m * DIMK + k] = hi;
    g_omTl[m * DIMK + k] = __float2bfloat16(lo);
    if (blockIdx.x == 0) {
        if (threadIdx.x < MFEAT) g_Ksum[threadIdx.x] = 0.0f;
        if (threadIdx.x == 0)    g_maxbits = 0u;
    }
}

// ---------------- warp-mma helper -------------------------------------------
__device__ __forceinline__ void mma16816(float* d, const unsigned* a, const unsigned* b) {
    asm volatile(
        "mma.sync.aligned.m16n8k16.row.col.f32.bf16.bf16.f32 "
        "{%0,%1,%2,%3},{%4,%5,%6,%7},{%8,%9},{%0,%1,%2,%3};\n"
        : "+f"(d[0]), "+f"(d[1]), "+f"(d[2]), "+f"(d[3])
        : "r"(a[0]), "r"(a[1]), "r"(a[2]), "r"(a[3]), "r"(b[0]), "r"(b[1]));
}

// ---------------- kernel 1/3: U = (X * d^-1/4) @ omega via bf16-split MMA ----
// CTA: 64 rows x 256 feats, 8 warps (4 feat-warps x 2 row-warps).
// A = omegaT (feat-major, k contiguous), B = X rows (k contiguous).
__global__ __launch_bounds__(256, 1)
void gemm_mma(const float* __restrict__ X,
              float* __restrict__ U,
              float* __restrict__ hout,
              int trackMax) {
    extern __shared__ __nv_bfloat16 sm[];
    __nv_bfloat16* sXh = sm;                          // 64 * 136
    __nv_bfloat16* sXl = sXh + 64 * SX_STRIDE;
    __nv_bfloat16* sOh = sXl + 64 * SX_STRIDE;        // 256 * 136
    __nv_bfloat16* sOl = sOh + 256 * SO_STRIDE;

    const int tid   = threadIdx.x;
    const int lane  = tid & 31;
    const int wid   = tid >> 5;
    const int rowg0 = blockIdx.x * 64;
    const float invD4 = 0.2973017787506803f;          // 128^-0.25

    // ---- stage X tile (64 x 128 fp32 -> bf16 hi/lo), compute h per row ----
    {
        const int r   = tid >> 2;                     // 0..63
        const int seg = (tid & 3) * 32;               // 32 floats per thread
        const float4* src = (const float4*)(X + (size_t)(rowg0 + r) * DIMK + seg);
        float h = 0.0f;
        #pragma unroll
        for (int i = 0; i < 8; ++i) {
            float4 v = src[i];
            v.x *= invD4; v.y *= invD4; v.z *= invD4; v.w *= invD4;
            h += v.x*v.x + v.y*v.y + v.z*v.z + v.w*v.w;
            const int c = seg + i * 4;
            __nv_bfloat162 h2a, l2a, h2b, l2b;
            h2a.x = __float2bfloat16(v.x);  h2a.y = __float2bfloat16(v.y);
            l2a.x = __float2bfloat16(v.x - __bfloat162float(h2a.x));
            l2a.y = __float2bfloat16(v.y - __bfloat162float(h2a.y));
            h2b.x = __float2bfloat16(v.z);  h2b.y = __float2bfloat16(v.w);
            l2b.x = __float2bfloat16(v.z - __bfloat162float(h2b.x));
            l2b.y = __float2bfloat16(v.w - __bfloat162float(h2b.y));
            *(__nv_bfloat162*)&sXh[r * SX_STRIDE + c]     = h2a;
            *(__nv_bfloat162*)&sXh[r * SX_STRIDE + c + 2] = h2b;
            *(__nv_bfloat162*)&sXl[r * SX_STRIDE + c]     = l2a;
            *(__nv_bfloat162*)&sXl[r * SX_STRIDE + c + 2] = l2b;
        }
        h += __shfl_xor_sync(0xFFFFFFFFu, h, 1);
        h += __shfl_xor_sync(0xFFFFFFFFu, h, 2);
        if ((tid & 3) == 0) hout[rowg0 + r] = 0.5f * h;   // sum(x^2)/(2 sqrt d)
    }

    // ---- stage omegaT hi/lo into padded smem (32-bit copies) ----
    {
        const unsigned* gOh = (const unsigned*)g_omTh;
        const unsigned* gOl = (const unsigned*)g_omTl;
        unsigned* dOh = (unsigned*)sOh;
        unsigned* dOl = (unsigned*)sOl;
        #pragma unroll
        for (int i = tid; i < MFEAT * DIMK / 2; i += 256) {
            const int f  = i >> 6;            // feat
            const int kw = i & 63;            // k word (2 bf16)
            dOh[f * (SO_STRIDE / 2) + kw] = gOh[i];
            dOl[f * (SO_STRIDE / 2) + kw] = gOl[i];
        }
    }
    __syncthreads();

    // ---- MMA mainloop ----
    const int featW = (wid & 3) * 64;     // warp's feature base (4 m16-tiles)
    const int rowW  = (wid >> 2) * 32;    // warp's row base     (4 n8-tiles)
    const int q     = lane >> 2;
    const int kk    = 2 * (lane & 3);

    float acc[4][4][4];
    #pragma unroll
    for (int mi = 0; mi < 4; ++mi)
        #pragma unroll
        for (int ni = 0; ni < 4; ++ni)
            #pragma unroll
            for (int j = 0; j < 4; ++j) acc[mi][ni][j] = 0.0f;

    #pragma unroll
    for (int k0 = 0; k0 < DIMK; k0 += 16) {
        unsigned ah[4][4], al[4][4], bh[4][2], bl[4][2];
        const int kr = k0 + kk;
        #pragma unroll
        for (int mi = 0; mi < 4; ++mi) {
            const int f = featW + mi * 16 + q;
            const __nv_bfloat16* p0 = &sOh[f * SO_STRIDE + kr];
            const __nv_bfloat16* p1 = &sOh[(f + 8) * SO_STRIDE + kr];
            ah[mi][0] = *(const unsigned*)p0;
            ah[mi][1] = *(const unsigned*)p1;
            ah[mi][2] = *(const unsigned*)(p0 + 8);
            ah[mi][3] = *(const unsigned*)(p1 + 8);
            const __nv_bfloat16* q0 = &sOl[f * SO_STRIDE + kr];
            const __nv_bfloat16* q1 = &sOl[(f + 8) * SO_STRIDE + kr];
            al[mi][0] = *(const unsigned*)q0;
            al[mi][1] = *(const unsigned*)q1;
            al[mi][2] = *(const unsigned*)(q0 + 8);
            al[mi][3] = *(const unsigned*)(q1 + 8);
        }
        #pragma unroll
        for (int ni = 0; ni < 4; ++ni) {
            const int r = rowW + ni * 8 + q;
            const __nv_bfloat16* p = &sXh[r * SX_STRIDE + kr];
            bh[ni][0] = *(const unsigned*)p;
            bh[ni][1] = *(const unsigned*)(p + 8);
            const __nv_bfloat16* pl = &sXl[r * SX_STRIDE + kr];
            bl[ni][0] = *(const unsigned*)pl;
            bl[ni][1] = *(const unsigned*)(pl + 8);
        }
        #pragma unroll
        for (int mi = 0; mi < 4; ++mi)
            #pragma unroll
            for (int ni = 0; ni < 4; ++ni) {
                mma16816(acc[mi][ni], ah[mi], bh[ni]);   // hi * hi
                mma16816(acc[mi][ni], ah[mi], bl[ni]);   // hi * lo
                mma16816(acc[mi][ni], al[mi], bh[ni]);   // lo * hi
            }
    }

    // ---- epilogue: store U[row][feat]; optional global max ----
    float mx = -INFINITY;
    #pragma unroll
    for (int mi = 0; mi < 4; ++mi)
        #pragma unroll
        for (int ni = 0; ni < 4; ++ni) {
            const int f = featW + mi * 16 + q;
            const int r = rowg0 + rowW + ni * 8 + 2 * (lane & 3);
            float* p = U + (size_t)r * MFEAT + f;
            p[0]         = acc[mi][ni][0];
            p[MFEAT]     = acc[mi][ni][1];
            p[8]         = acc[mi][ni][2];
            p[MFEAT + 8] = acc[mi][ni][3];
            if (trackMax) {
                mx = fmaxf(mx, fmaxf(fmaxf(acc[mi][ni][0], acc[mi][ni][1]),
                                     fmaxf(acc[mi][ni][2], acc[mi][ni][3])));
            }
        }

    if (trackMax) {
        __shared__ float s_red[8];
        #pragma unroll
        for (int o = 16; o > 0; o >>= 1)
            mx = fmaxf(mx, __shfl_xor_sync(0xFFFFFFFFu, mx, o));
        if (lane == 0) s_red[wid] = mx;
        __syncthreads();
        if (tid == 0) {
            float bm = s_red[0];
            #pragma unroll
            for (int i = 1; i < 8; ++i) bm = fmaxf(bm, s_red[i]);
            atomicMax(&g_maxbits, fkey(bm));
        }
    }
}

// ---------------- kernel 2: Kp = (exp(U-h-M)+1e-4)/16 in place, + Ksum ------
__global__ void kp_kernel() {
    const int f  = threadIdx.x;                 // 256 threads = 256 features
    const int r0 = blockIdx.x * 256;
    const float M = fdecode(g_maxbits);
    float sum = 0.0f;
    for (int i = 0; i < 256; ++i) {
        const int r = r0 + i;
        const size_t idx = (size_t)r * MFEAT + f;
        const float kp = (expf(g_UK[idx] - g_hK[r] - M) + 1e-4f) * 0.0625f;
        g_UK[idx] = kp;
        sum += kp;
    }
    atomicAdd(&g_Ksum[f], sum);
}

// ---------------- kernel 4: fused epilogue, one warp per row ----------------
__global__ void final_kernel(const float* __restrict__ V,
                             float* __restrict__ out) {
    const int gwarp = (blockIdx.x * blockDim.x + threadIdx.x) >> 5;  // row
    const int lane  = threadIdx.x & 31;
    const size_t base = (size_t)gwarp * MFEAT;

    float u[8];
    float mxr = -INFINITY;
    #pragma unroll
    for (int j = 0; j < 8; ++j) {
        u[j] = g_UQ[base + lane + 32 * j];
        mxr = fmaxf(mxr, u[j]);
    }
    #pragma unroll
    for (int o = 16; o > 0; o >>= 1)
        mxr = fmaxf(mxr, __shfl_xor_sync(0xFFFFFFFFu, mxr, o));

    const float h = g_hQ[gwarp];
    float w = 0.0f, nrm = 0.0f;
    #pragma unroll
    for (int j = 0; j < 8; ++j) {
        const float qp = (expf(u[j] - h - mxr) + 1e-4f) * 0.0625f;
        w   += qp * g_UK[base + lane + 32 * j];   // g_UK holds Kp now
        nrm += qp * g_Ksum[lane + 32 * j];
    }
    #pragma unroll
    for (int o = 16; o > 0; o >>= 1) {
        w   += __shfl_xor_sync(0xFFFFFFFFu, w,   o);
        nrm += __shfl_xor_sync(0xFFFFFFFFu, nrm, o);
    }
    nrm += 1e-8f;
    const float scale = w / nrm;

    const float4 v4 = ((const float4*)(V + (size_t)gwarp * DIMK))[lane];
    float4 o4;
    o4.x = v4.x * scale; o4.y = v4.y * scale;
    o4.z = v4.z * scale; o4.w = v4.w * scale;
    ((float4*)(out + (size_t)gwarp * DIMK))[lane] = o4;
}

// ---------------- launch ----------------------------------------------------
extern "C" void kernel_launch(void* const* d_in, const int* in_sizes, int n_in,
                              void* d_out, int out_size) {
    const float* Q     = (const float*)d_in[0];
    const float* K     = (const float*)d_in[1];
    const float* V     = (const float*)d_in[2];
    const float* omega = (const float*)d_in[3];
    float* out = (float*)d_out;

    const int smem = (64 * SX_STRIDE * 2 + 256 * SO_STRIDE * 2) * (int)sizeof(__nv_bfloat16);
    cudaFuncSetAttribute(gemm_mma,
                         cudaFuncAttributeMaxDynamicSharedMemorySize, smem);

    float* UK = nullptr; float* UQ = nullptr;
    float* hK = nullptr; float* hQ = nullptr;
    cudaGetSymbolAddress((void**)&UK, g_UK);
    cudaGetSymbolAddress((void**)&UQ, g_UQ);
    cudaGetSymbolAddress((void**)&hK, g_hK);
    cudaGetSymbolAddress((void**)&hQ, g_hQ);

    init_kernel<<<128, 256>>>(omega);
    gemm_mma<<<NROWS / 64, 256, smem>>>(K, UK, hK, 1);
    kp_kernel<<<NROWS / 256, 256>>>();
    gemm_mma<<<NROWS / 64, 256, smem>>>(Q, UQ, hQ, 0);
    final_kernel<<<NROWS / 8, 256>>>(V, out);
}